// round 14
// baseline (speedup 1.0000x reference)
#include <cuda_runtime.h>
#include <cuda_fp16.h>
#include <cstdint>

#define HEADS 8
#define DIM   64
#define TMAXP 4096
#define BM    128
#define BN    64
#define NT    256

// smem layout (bytes): swizzled 128B rows
#define S_QH 0
#define S_KV 16384            // + stage*KV_STAGE, 3 stages
#define KV_STAGE 16384
#define T_KH 0
#define T_VH 8192
#define S_RS 65536
#define S_RE 66048
#define SMEM_BYTES 66560
// epilogue exchange (reuses KV stage area after the loop)
#define S_OEX S_KV                      // 128*68*4 = 34816
#define S_LEX (S_KV + 34816)            // 128*4

#define MASKV -3.0e38f

// ---------------- scratch (fp16) ----------------
__device__ __align__(16) __half g_Qh[(size_t)HEADS * TMAXP * DIM];
__device__ __align__(16) __half g_Kh[(size_t)HEADS * TMAXP * DIM];
__device__ __align__(16) __half g_Vh[(size_t)HEADS * TMAXP * DIM];

// ---------------- helpers ----------------
__device__ __forceinline__ float ex2(float x) {
    float r;
    asm("ex2.approx.ftz.f32 %0, %1;" : "=f"(r) : "f"(x));
    return r;
}
__device__ __forceinline__ uint32_t smem_u32(const void* p) {
    uint32_t a;
    asm("{ .reg .u64 t; cvta.to.shared.u64 t, %1; cvt.u32.u64 %0, t; }" : "=r"(a) : "l"(p));
    return a;
}
__device__ __forceinline__ void ldsm_x4(uint32_t& r0, uint32_t& r1, uint32_t& r2, uint32_t& r3, uint32_t a) {
    asm volatile("ldmatrix.sync.aligned.m8n8.x4.shared.b16 {%0,%1,%2,%3}, [%4];"
                 : "=r"(r0), "=r"(r1), "=r"(r2), "=r"(r3) : "r"(a));
}
__device__ __forceinline__ void ldsm_x4t(uint32_t& r0, uint32_t& r1, uint32_t& r2, uint32_t& r3, uint32_t a) {
    asm volatile("ldmatrix.sync.aligned.m8n8.x4.trans.shared.b16 {%0,%1,%2,%3}, [%4];"
                 : "=r"(r0), "=r"(r1), "=r"(r2), "=r"(r3) : "r"(a));
}
__device__ __forceinline__ void mma_f16(float* c, const uint32_t* a, const uint32_t* b) {
    asm volatile("mma.sync.aligned.m16n8k16.row.col.f32.f16.f16.f32 "
                 "{%0,%1,%2,%3}, {%4,%5,%6,%7}, {%8,%9}, {%0,%1,%2,%3};"
                 : "+f"(c[0]), "+f"(c[1]), "+f"(c[2]), "+f"(c[3])
                 : "r"(a[0]), "r"(a[1]), "r"(a[2]), "r"(a[3]), "r"(b[0]), "r"(b[1]));
}
// pack two floats to fp16x2 (lo = a, hi = b)
__device__ __forceinline__ uint32_t packh2(float a, float b) {
    uint32_t r;
    asm("cvt.rn.f16x2.f32 %0, %1, %2;" : "=r"(r) : "f"(b), "f"(a));
    return r;
}
#define CP_ASYNC(dst, src, sz) \
    asm volatile("cp.async.cg.shared.global [%0], [%1], 16, %2;" :: "r"(dst), "l"(src), "r"(sz))
#define CP_COMMIT() asm volatile("cp.async.commit_group;" ::: "memory")
#define CP_WAIT0()  asm volatile("cp.async.wait_group 0;" ::: "memory")
#define CP_WAIT1()  asm volatile("cp.async.wait_group 1;" ::: "memory")

// ---------------- prep: fp32 qkv -> fp16 (Q scaled, K, V) ----------------
__global__ void prep(const float* __restrict__ qkv, int T) {
    int idx = blockIdx.x * blockDim.x + threadIdx.x;
    if (idx >= T * HEADS * 16) return;
    int d4 = idx & 15;
    int h  = (idx >> 4) & (HEADS - 1);
    int t  = idx >> 7;
    const size_t gin = (size_t)t * 1536 + h * 64 + d4 * 4;
    const float4 q = *(const float4*)(qkv + gin);
    const float4 k = *(const float4*)(qkv + gin + 512);
    const float4 v = *(const float4*)(qkv + gin + 1024);
    size_t base = ((size_t)h * TMAXP + t) * DIM + d4 * 4;
    const float s = 0.125f * 1.4426950408889634f;  // 1/sqrt(64) * log2(e)
    *(uint2*)(g_Qh + base) = make_uint2(packh2(q.x * s, q.y * s), packh2(q.z * s, q.w * s));
    *(uint2*)(g_Kh + base) = make_uint2(packh2(k.x, k.y), packh2(k.z, k.w));
    *(uint2*)(g_Vh + base) = make_uint2(packh2(v.x, v.y), packh2(v.z, v.w));
}

// ---------------- main attention: 8 warps = 4M x 2N, BM=128 ----------------
__global__ __launch_bounds__(NT, 2)
void attn_main(const int* __restrict__ cu, int nseg, int T, float* __restrict__ out)
{
    extern __shared__ char smem[];
    const uint32_t sb = smem_u32(smem);
    const int tid = threadIdx.x, wid = tid >> 5, lane = tid & 31;
    const int mg = wid & 3;        // m-group 0..3 (16 rows each; rows mg*16 + [0,16) and +64? no: 4 groups x 16 = 64... see below)
    const int nh = wid >> 2;       // kv-half 0/1 (32 cols each)
    const int q0 = blockIdx.x * BM;
    const int h  = blockIdx.y;
    int* rs_s = (int*)(smem + S_RS);
    int* re_s = (int*)(smem + S_RE);

    // Each warp handles 32 q-rows: mg selects rows [mg*32, mg*32+32) via two
    // m16 tiles? No — keep 16 rows/warp x 4 groups only covers 64. BM=128 needs
    // 8 m-groups of 16. Solution: each warp-pair (mg, nh) covers rows
    // mg*16 and mg*16+64 — i.e. warp owns TWO 16-row m-tiles (o doubles? no).
    // Simpler: each of 4 m-groups covers 32 rows as two 16-row tiles stacked.
    const int m0 = mg * 32;       // this warp: rows [m0, m0+32)

    // stage Q tile (128 rows), swizzled
    {
        const uint4* qh = (const uint4*)(g_Qh + ((size_t)h * TMAXP + q0) * DIM);
        #pragma unroll
        for (int p = 0; p < 4; p++) {
            int i = tid + p * NT;
            int row = i >> 3, c = i & 7;
            uint32_t soff = (uint32_t)(row * 128 + ((c ^ (row & 7)) << 4));
            if (q0 + row < T) *(uint4*)(smem + S_QH + soff) = qh[i];
            else              *(uint4*)(smem + S_QH + soff) = make_uint4(0, 0, 0, 0);
        }
    }
    if (tid < BM) {
        int t = q0 + tid; if (t > T - 1) t = T - 1;
        int s = 0;
        for (int i = 0; i < nseg; i++) if (t >= cu[i]) s = i;
        rs_s[tid] = cu[s]; re_s[tid] = cu[s + 1];
    }
    __syncthreads();
    const int kvlo = rs_s[0];
    const int kvhi = re_s[BM - 1];

    // rows owned: r0, r0+8 (tile A = rows m0..m0+16), r0+16, r0+24 (tile B)
    const int r0 = m0 + (lane >> 2);
    const int lo0 = rs_s[r0],      hi0 = re_s[r0];
    const int lo1 = rs_s[r0 + 8],  hi1 = re_s[r0 + 8];
    const int lo2 = rs_s[r0 + 16], hi2 = re_s[r0 + 16];
    const int lo3 = rs_s[r0 + 24], hi3 = re_s[r0 + 24];
    int lomax = lo0 > lo1 ? lo0 : lo1;
    lomax = lomax > lo2 ? lomax : lo2;
    lomax = lomax > lo3 ? lomax : lo3;
    int himin = hi0 < hi1 ? hi0 : hi1;
    himin = himin < hi2 ? himin : hi2;
    himin = himin < hi3 ? himin : hi3;

    const __half* gKH = g_Kh + (size_t)h * TMAXP * DIM;
    const __half* gVH = g_Vh + (size_t)h * TMAXP * DIM;

    // cp.async staging geometry (64 kv rows x 8 chunks per tensor, 256 threads)
    const int cpc   = tid & 7;
    const int cprow0 = tid >> 3;          // 0..31
    const int cprow1 = cprow0 + 32;       // 32..63
    const uint32_t cpoff0 = (uint32_t)(cprow0 * 128 + ((cpc ^ (cprow0 & 7)) << 4));
    const uint32_t cpoff1 = (uint32_t)(cprow1 * 128 + ((cpc ^ (cprow1 & 7)) << 4));
    const int cpg0 = cprow0 * 64 + cpc * 8;
    const int cpg1 = cprow1 * 64 + cpc * 8;

    // fragment address invariants
    const int swz = lane & 7;
    const uint32_t qrowA = (uint32_t)((m0 + (lane & 15)) * 128);
    const uint32_t qrowB = qrowA + 16 * 128;
    const int qcc = lane >> 4;
    // K: this warp reads kv rows [nh*32, nh*32+32)
    const uint32_t krow4 = (uint32_t)((nh * 32 + (lane >> 4) * 8 + (lane & 7)) * 128);
    const int khalf = (lane >> 3) & 1;
    const uint32_t vrow4 = (uint32_t)((nh * 32 + ((lane >> 3) & 1) * 8 + (lane & 7)) * 128);
    const int vnsel = lane >> 4;

    // ---- hoist Q fragments for both m-tiles (loop-invariant) ----
    uint32_t qfA[4][4], qfB[4][4];
    #pragma unroll
    for (int c = 0; c < 4; c++) {
        uint32_t coff = (uint32_t)(((qcc + 2 * c) ^ swz) << 4);
        ldsm_x4(qfA[c][0], qfA[c][1], qfA[c][2], qfA[c][3], sb + S_QH + qrowA + coff);
        ldsm_x4(qfB[c][0], qfB[c][1], qfB[c][2], qfB[c][3], sb + S_QH + qrowB + coff);
    }

    float l01 = 0.f, l11 = 0.f, l21 = 0.f, l31 = 0.f;
    float o[8][4], o2[8][4];
    #pragma unroll
    for (int n = 0; n < 8; n++)
        #pragma unroll
        for (int e = 0; e < 4; e++) { o[n][e] = 0.f; o2[n][e] = 0.f; }

    const uint32_t ones2[2] = { 0x3C003C00u, 0x3C003C00u };

    const int nIter = (kvhi - kvlo + BN - 1) / BN;

    // prologue: stage tiles 0 and 1
    #pragma unroll
    for (int pre = 0; pre < 2; pre++) {
        if (pre < nIter) {
            const int kb = kvlo + pre * BN;
            uint32_t dbase = sb + S_KV + (uint32_t)(pre * KV_STAGE);
            int sz0 = (kb + cprow0 < kvhi) ? 16 : 0;
            int sz1 = (kb + cprow1 < kvhi) ? 16 : 0;
            CP_ASYNC(dbase + T_KH + cpoff0, gKH + (size_t)kb * DIM + cpg0, sz0);
            CP_ASYNC(dbase + T_KH + cpoff1, gKH + (size_t)kb * DIM + cpg1, sz1);
            CP_ASYNC(dbase + T_VH + cpoff0, gVH + (size_t)kb * DIM + cpg0, sz0);
            CP_ASYNC(dbase + T_VH + cpoff1, gVH + (size_t)kb * DIM + cpg1, sz1);
        }
        CP_COMMIT();
    }

    for (int it = 0; it < nIter; it++) {
        const int kb = kvlo + it * BN;

        if (it + 1 < nIter) { CP_WAIT1(); } else { CP_WAIT0(); }
        __syncthreads();

        if (it + 2 < nIter) {
            const int kn = kb + 2 * BN;
            uint32_t dbase = sb + S_KV + (uint32_t)(((it + 2) % 3) * KV_STAGE);
            int sz0 = (kn + cprow0 < kvhi) ? 16 : 0;
            int sz1 = (kn + cprow1 < kvhi) ? 16 : 0;
            CP_ASYNC(dbase + T_KH + cpoff0, gKH + (size_t)kn * DIM + cpg0, sz0);
            CP_ASYNC(dbase + T_KH + cpoff1, gKH + (size_t)kn * DIM + cpg1, sz1);
            CP_ASYNC(dbase + T_VH + cpoff0, gVH + (size_t)kn * DIM + cpg0, sz0);
            CP_ASYNC(dbase + T_VH + cpoff1, gVH + (size_t)kn * DIM + cpg1, sz1);
            CP_COMMIT();
        }

        const uint32_t kvb = sb + S_KV + (uint32_t)((it % 3) * KV_STAGE);
        const uint32_t kbase = kvb + T_KH + krow4;
        const uint32_t vbase = kvb + T_VH + vrow4;

        // ---- MMA1: S for 32 q-rows x this warp's 32 kv cols ----
        float sA[4][4], sB[4][4];
        #pragma unroll
        for (int n = 0; n < 4; n++)
            #pragma unroll
            for (int e = 0; e < 4; e++) { sA[n][e] = 0.f; sB[n][e] = 0.f; }

        #pragma unroll
        for (int c = 0; c < 4; c++) {
            const uint32_t kchunk = (uint32_t)(((khalf + 2 * c) ^ swz) << 4);
            uint32_t kf[2][4];
            #pragma unroll
            for (int jp = 0; jp < 2; jp++)
                ldsm_x4(kf[jp][0], kf[jp][1], kf[jp][2], kf[jp][3],
                        kbase + (uint32_t)(jp * 2048) + kchunk);
            #pragma unroll
            for (int jp = 0; jp < 2; jp++) {
                mma_f16(sA[2 * jp],     qfA[c], kf[jp]);
                mma_f16(sA[2 * jp + 1], qfA[c], kf[jp] + 2);
                mma_f16(sB[2 * jp],     qfB[c], kf[jp]);
                mma_f16(sB[2 * jp + 1], qfB[c], kf[jp] + 2);
            }
        }

        // ---- boundary tiles only: clamp invalid entries ----
        if (kb < lomax || kb + BN > himin) {
            const int clo0 = lo0 - kb, chi0 = hi0 - kb;
            const int clo1 = lo1 - kb, chi1 = hi1 - kb;
            const int clo2 = lo2 - kb, chi2 = hi2 - kb;
            const int clo3 = lo3 - kb, chi3 = hi3 - kb;
            #pragma unroll
            for (int j = 0; j < 4; j++) {
                int cb = nh * 32 + j * 8 + (lane & 3) * 2;
                if (cb < clo0     || cb >= chi0)     sA[j][0] = MASKV;
                if (cb + 1 < clo0 || cb + 1 >= chi0) sA[j][1] = MASKV;
                if (cb < clo1     || cb >= chi1)     sA[j][2] = MASKV;
                if (cb + 1 < clo1 || cb + 1 >= chi1) sA[j][3] = MASKV;
                if (cb < clo2     || cb >= chi2)     sB[j][0] = MASKV;
                if (cb + 1 < clo2 || cb + 1 >= chi2) sB[j][1] = MASKV;
                if (cb < clo3     || cb >= chi3)     sB[j][2] = MASKV;
                if (cb + 1 < clo3 || cb + 1 >= chi3) sB[j][3] = MASKV;
            }
        }

        // ---- fixed-max softmax: P = exp2(s); MMA2 over warp's kv half ----
        float lsA[4] = { 0.f, 0.f, 0.f, 0.f };
        float lsB[4] = { 0.f, 0.f, 0.f, 0.f };
        #pragma unroll
        for (int kc = 0; kc < 2; kc++) {
            uint32_t vf[4][4];
            uint32_t vcbase = vbase + (uint32_t)(kc * 2048);
            #pragma unroll
            for (int np = 0; np < 4; np++)
                ldsm_x4t(vf[np][0], vf[np][1], vf[np][2], vf[np][3],
                         vcbase + (uint32_t)(((2 * np + vnsel) ^ swz) << 4));
            uint32_t paA[4], paB[4];
            #pragma unroll
            for (int jj = 0; jj < 2; jj++) {
                int j = 2 * kc + jj;
                paA[2 * jj]     = packh2(ex2(sA[j][0]), ex2(sA[j][1]));
                paA[2 * jj + 1] = packh2(ex2(sA[j][2]), ex2(sA[j][3]));
                paB[2 * jj]     = packh2(ex2(sB[j][0]), ex2(sB[j][1]));
                paB[2 * jj + 1] = packh2(ex2(sB[j][2]), ex2(sB[j][3]));
            }
            mma_f16(lsA, paA, ones2);
            mma_f16(lsB, paB, ones2);
            #pragma unroll
            for (int np = 0; np < 4; np++) {
                mma_f16(o[2 * np],      paA, vf[np]);
                mma_f16(o[2 * np + 1],  paA, vf[np] + 2);
                mma_f16(o2[2 * np],     paB, vf[np]);
                mma_f16(o2[2 * np + 1], paB, vf[np] + 2);
            }
        }
        l01 += lsA[0]; l11 += lsA[2];
        l21 += lsB[0]; l31 += lsB[2];
    }

    // ---- epilogue: cross-warp (kv-half) reduction via smem ----
    float* osm = (float*)(smem + S_OEX);   // [128][68]
    float* lsm = (float*)(smem + S_LEX);   // [128]
    const int colb = (lane & 3) * 2;
    __syncthreads();   // everyone done reading KV stages
    if (nh == 1) {
        #pragma unroll
        for (int n = 0; n < 8; n++) {
            *(float2*)&osm[r0 * 68 + n * 8 + colb]        = make_float2(o[n][0],  o[n][1]);
            *(float2*)&osm[(r0 + 8) * 68 + n * 8 + colb]  = make_float2(o[n][2],  o[n][3]);
            *(float2*)&osm[(r0 + 16) * 68 + n * 8 + colb] = make_float2(o2[n][0], o2[n][1]);
            *(float2*)&osm[(r0 + 24) * 68 + n * 8 + colb] = make_float2(o2[n][2], o2[n][3]);
        }
        if ((lane & 3) == 0) {
            lsm[r0] = l01; lsm[r0 + 8] = l11;
            lsm[r0 + 16] = l21; lsm[r0 + 24] = l31;
        }
    }
    __syncthreads();
    if (nh == 0) {
        float lt0 = l01 + lsm[r0];
        float lt1 = l11 + lsm[r0 + 8];
        float lt2 = l21 + lsm[r0 + 16];
        float lt3 = l31 + lsm[r0 + 24];
        float inv0 = lt0 > 0.f ? 1.f / lt0 : 0.f;
        float inv1 = lt1 > 0.f ? 1.f / lt1 : 0.f;
        float inv2 = lt2 > 0.f ? 1.f / lt2 : 0.f;
        float inv3 = lt3 > 0.f ? 1.f / lt3 : 0.f;
        const int t0 = q0 + r0;
        #pragma unroll
        for (int rr = 0; rr < 4; rr++) {
            int t = t0 + rr * 8;
            if (t >= T) continue;
            float inv = rr == 0 ? inv0 : rr == 1 ? inv1 : rr == 2 ? inv2 : inv3;
            float* op = out + (size_t)t * (HEADS * DIM) + h * DIM + colb;
            float* src0 = (rr < 2) ? &o[0][ (rr & 1) * 2 ] : &o2[0][ (rr & 1) * 2 ];
            #pragma unroll
            for (int n = 0; n < 8; n++) {
                float a0 = (rr == 0) ? o[n][0] : (rr == 1) ? o[n][2] : (rr == 2) ? o2[n][0] : o2[n][2];
                float a1 = (rr == 0) ? o[n][1] : (rr == 1) ? o[n][3] : (rr == 2) ? o2[n][1] : o2[n][3];
                float2 p = *(float2*)&osm[(r0 + rr * 8) * 68 + n * 8 + colb];
                *(float2*)(op + n * 8) = make_float2((a0 + p.x) * inv, (a1 + p.y) * inv);
            }
            (void)src0;
        }
    }
}

// ---------------- launch ----------------
extern "C" void kernel_launch(void* const* d_in, const int* in_sizes, int n_in,
                              void* d_out, int out_size)
{
    const float* qkv = (const float*)d_in[0];
    const int*   cu  = (const int*)d_in[1];
    const int T    = in_sizes[0] / (3 * HEADS * DIM);
    const int nseg = in_sizes[1] - 1;

    static bool init = false;
    if (!init) {
        cudaFuncSetAttribute(attn_main, cudaFuncAttributeMaxDynamicSharedMemorySize, SMEM_BYTES);
        init = true;
    }

    prep<<<(T * HEADS * 16 + 255) / 256, 256>>>(qkv, T);
    attn_main<<<dim3((T + BM - 1) / BM, HEADS), NT, SMEM_BYTES>>>(cu, nseg, T, (float*)d_out);
}

// round 15
// speedup vs baseline: 1.4536x; 1.4536x over previous
#include <cuda_runtime.h>
#include <cuda_fp16.h>
#include <cstdint>

#define HEADS 8
#define DIM   64
#define TMAXP 4096
#define BM    128
#define BN    128            // staged tile (processed as 2x64 subtiles)
#define NT    256

// smem layout (bytes): swizzled 128B rows
#define S_QH 0               // 16384
#define S_KV 16384           // + stage*KV_STAGE, 3 stages of 32KB
#define KV_STAGE 32768
#define T_KH 0               // K: 128 rows x 128B
#define T_VH 16384           // V: 128 rows x 128B
#define S_RS 114688
#define S_RE 115200
#define SMEM_BYTES 115712    // x2 CTAs = 231424 <= 232448

#define MASKV -3.0e38f

// ---------------- scratch (fp16) ----------------
__device__ __align__(16) __half g_Qh[(size_t)HEADS * TMAXP * DIM];
__device__ __align__(16) __half g_Kh[(size_t)HEADS * TMAXP * DIM];
__device__ __align__(16) __half g_Vh[(size_t)HEADS * TMAXP * DIM];

// ---------------- helpers ----------------
__device__ __forceinline__ float ex2(float x) {
    float r;
    asm("ex2.approx.ftz.f32 %0, %1;" : "=f"(r) : "f"(x));
    return r;
}
__device__ __forceinline__ uint32_t smem_u32(const void* p) {
    uint32_t a;
    asm("{ .reg .u64 t; cvta.to.shared.u64 t, %1; cvt.u32.u64 %0, t; }" : "=r"(a) : "l"(p));
    return a;
}
__device__ __forceinline__ void ldsm_x4(uint32_t& r0, uint32_t& r1, uint32_t& r2, uint32_t& r3, uint32_t a) {
    asm volatile("ldmatrix.sync.aligned.m8n8.x4.shared.b16 {%0,%1,%2,%3}, [%4];"
                 : "=r"(r0), "=r"(r1), "=r"(r2), "=r"(r3) : "r"(a));
}
__device__ __forceinline__ void ldsm_x4t(uint32_t& r0, uint32_t& r1, uint32_t& r2, uint32_t& r3, uint32_t a) {
    asm volatile("ldmatrix.sync.aligned.m8n8.x4.trans.shared.b16 {%0,%1,%2,%3}, [%4];"
                 : "=r"(r0), "=r"(r1), "=r"(r2), "=r"(r3) : "r"(a));
}
__device__ __forceinline__ void mma_f16(float* c, const uint32_t* a, const uint32_t* b) {
    asm volatile("mma.sync.aligned.m16n8k16.row.col.f32.f16.f16.f32 "
                 "{%0,%1,%2,%3}, {%4,%5,%6,%7}, {%8,%9}, {%0,%1,%2,%3};"
                 : "+f"(c[0]), "+f"(c[1]), "+f"(c[2]), "+f"(c[3])
                 : "r"(a[0]), "r"(a[1]), "r"(a[2]), "r"(a[3]), "r"(b[0]), "r"(b[1]));
}
// pack two floats to fp16x2 (lo = a, hi = b)
__device__ __forceinline__ uint32_t packh2(float a, float b) {
    uint32_t r;
    asm("cvt.rn.f16x2.f32 %0, %1, %2;" : "=r"(r) : "f"(b), "f"(a));
    return r;
}
#define CP_ASYNC(dst, src, sz) \
    asm volatile("cp.async.cg.shared.global [%0], [%1], 16, %2;" :: "r"(dst), "l"(src), "r"(sz))
#define CP_COMMIT() asm volatile("cp.async.commit_group;" ::: "memory")
#define CP_WAIT0()  asm volatile("cp.async.wait_group 0;" ::: "memory")
#define CP_WAIT1()  asm volatile("cp.async.wait_group 1;" ::: "memory")

// ---------------- prep: fp32 qkv -> fp16 (Q scaled, K, V) ----------------
__global__ void prep(const float* __restrict__ qkv, int T) {
    int idx = blockIdx.x * blockDim.x + threadIdx.x;
    if (idx >= T * HEADS * 16) return;
    int d4 = idx & 15;
    int h  = (idx >> 4) & (HEADS - 1);
    int t  = idx >> 7;
    const size_t gin = (size_t)t * 1536 + h * 64 + d4 * 4;
    const float4 q = *(const float4*)(qkv + gin);
    const float4 k = *(const float4*)(qkv + gin + 512);
    const float4 v = *(const float4*)(qkv + gin + 1024);
    size_t base = ((size_t)h * TMAXP + t) * DIM + d4 * 4;
    const float s = 0.125f * 1.4426950408889634f;  // 1/sqrt(64) * log2(e)
    *(uint2*)(g_Qh + base) = make_uint2(packh2(q.x * s, q.y * s), packh2(q.z * s, q.w * s));
    *(uint2*)(g_Kh + base) = make_uint2(packh2(k.x, k.y), packh2(k.z, k.w));
    *(uint2*)(g_Vh + base) = make_uint2(packh2(v.x, v.y), packh2(v.z, v.w));
}

// ---------------- main attention ----------------
__global__ __launch_bounds__(NT, 2)
void attn_main(const int* __restrict__ cu, int nseg, int T, float* __restrict__ out)
{
    extern __shared__ char smem[];
    const uint32_t sb = smem_u32(smem);
    const int tid = threadIdx.x, wid = tid >> 5, lane = tid & 31;
    const int q0 = blockIdx.x * BM;
    const int h  = blockIdx.y;
    int* rs_s = (int*)(smem + S_RS);
    int* re_s = (int*)(smem + S_RE);

    // stage Q tile, swizzled
    {
        const uint4* qh = (const uint4*)(g_Qh + ((size_t)h * TMAXP + q0) * DIM);
        #pragma unroll
        for (int p = 0; p < 4; p++) {
            int i = tid + p * NT;
            int row = i >> 3, c = i & 7;
            uint32_t soff = (uint32_t)(row * 128 + ((c ^ (row & 7)) << 4));
            if (q0 + row < T) *(uint4*)(smem + S_QH + soff) = qh[i];
            else              *(uint4*)(smem + S_QH + soff) = make_uint4(0, 0, 0, 0);
        }
    }
    if (tid < BM) {
        int t = q0 + tid; if (t > T - 1) t = T - 1;
        int s = 0;
        for (int i = 0; i < nseg; i++) if (t >= cu[i]) s = i;
        rs_s[tid] = cu[s]; re_s[tid] = cu[s + 1];
    }
    __syncthreads();
    const int kvlo = rs_s[0];
    const int kvhi = re_s[BM - 1];

    const int m0 = wid * 16;
    const int r0 = m0 + (lane >> 2);
    const int lo0 = rs_s[r0],     hi0 = re_s[r0];
    const int lo1 = rs_s[r0 + 8], hi1 = re_s[r0 + 8];
    const int lomax = lo0 > lo1 ? lo0 : lo1;
    const int himin = hi0 < hi1 ? hi0 : hi1;

    const __half* gKH = g_Kh + (size_t)h * TMAXP * DIM;
    const __half* gVH = g_Vh + (size_t)h * TMAXP * DIM;

    // cp.async staging geometry: 128 rows x 8 chunks, 256 threads -> 4 rows each
    const int cpc   = tid & 7;
    const int cprow = tid >> 3;           // 0..31; handles rows cprow + rr*32
    const uint32_t cpoff0 = (uint32_t)(cprow * 128 + ((cpc ^ (cprow & 7)) << 4));
    const int cpg0 = cprow * 64 + cpc * 8;

    // fragment address invariants (within a 64-row subtile)
    const int swz = lane & 7;
    const uint32_t qrow = (uint32_t)((m0 + (lane & 15)) * 128);
    const int qcc = lane >> 4;
    const uint32_t krow4 = (uint32_t)((((lane >> 4) * 8) + (lane & 7)) * 128);
    const int khalf = (lane >> 3) & 1;
    const uint32_t vrow4 = (uint32_t)(((((lane >> 3) & 1) * 8) + (lane & 7)) * 128);
    const int vnsel = lane >> 4;

    // ---- hoist Q fragments (loop-invariant) ----
    uint32_t qf[4][4];
    #pragma unroll
    for (int c = 0; c < 4; c++) {
        uint32_t qaddr = sb + S_QH + qrow + (uint32_t)(((qcc + 2 * c) ^ swz) << 4);
        ldsm_x4(qf[c][0], qf[c][1], qf[c][2], qf[c][3], qaddr);
    }

    float l0r = 0.f, l1r = 0.f;
    float o[8][4];
    #pragma unroll
    for (int n = 0; n < 8; n++)
        #pragma unroll
        for (int e = 0; e < 4; e++) o[n][e] = 0.f;

    const int nIter = (kvhi - kvlo + BN - 1) / BN;

    // prologue: stage tiles 0 and 1
    #pragma unroll
    for (int pre = 0; pre < 2; pre++) {
        if (pre < nIter) {
            const int kb = kvlo + pre * BN;
            uint32_t dbase = sb + S_KV + (uint32_t)(pre * KV_STAGE);
            #pragma unroll
            for (int rr = 0; rr < 4; rr++) {
                int row = cprow + rr * 32;
                uint32_t off = cpoff0 + (uint32_t)(rr * 4096);
                int g = cpg0 + rr * 2048;
                int sz = (kb + row < kvhi) ? 16 : 0;
                CP_ASYNC(dbase + T_KH + off, gKH + (size_t)kb * DIM + g, sz);
                CP_ASYNC(dbase + T_VH + off, gVH + (size_t)kb * DIM + g, sz);
            }
        }
        CP_COMMIT();
    }

    for (int it = 0; it < nIter; it++) {
        const int kb = kvlo + it * BN;

        if (it + 1 < nIter) { CP_WAIT1(); } else { CP_WAIT0(); }
        __syncthreads();

        if (it + 2 < nIter) {
            const int kn = kb + 2 * BN;
            uint32_t dbase = sb + S_KV + (uint32_t)(((it + 2) % 3) * KV_STAGE);
            #pragma unroll
            for (int rr = 0; rr < 4; rr++) {
                int row = cprow + rr * 32;
                uint32_t off = cpoff0 + (uint32_t)(rr * 4096);
                int g = cpg0 + rr * 2048;
                int sz = (kn + row < kvhi) ? 16 : 0;
                CP_ASYNC(dbase + T_KH + off, gKH + (size_t)kn * DIM + g, sz);
                CP_ASYNC(dbase + T_VH + off, gVH + (size_t)kn * DIM + g, sz);
            }
            CP_COMMIT();
        }

        const uint32_t kvb = sb + S_KV + (uint32_t)((it % 3) * KV_STAGE);

        // ---- two 64-col subtiles per staged tile ----
        #pragma unroll
        for (int half = 0; half < 2; half++) {
            const int kbs = kb + half * 64;
            const uint32_t kbase = kvb + T_KH + (uint32_t)(half * 8192) + krow4;
            const uint32_t vbase = kvb + T_VH + (uint32_t)(half * 8192) + vrow4;

            // ---- MMA1: S = Q K^T ----
            float s[8][4];
            #pragma unroll
            for (int n = 0; n < 8; n++)
                #pragma unroll
                for (int e = 0; e < 4; e++) s[n][e] = 0.f;

            #pragma unroll
            for (int c = 0; c < 4; c++) {
                const uint32_t kchunk = (uint32_t)(((khalf + 2 * c) ^ swz) << 4);
                uint32_t kf[4][4];
                #pragma unroll
                for (int jp = 0; jp < 4; jp++)
                    ldsm_x4(kf[jp][0], kf[jp][1], kf[jp][2], kf[jp][3],
                            kbase + (uint32_t)(jp * 2048) + kchunk);
                #pragma unroll
                for (int jp = 0; jp < 4; jp++) {
                    mma_f16(s[2 * jp],     qf[c], kf[jp]);
                    mma_f16(s[2 * jp + 1], qf[c], kf[jp] + 2);
                }
            }

            // ---- boundary subtiles only: clamp invalid entries ----
            if (kbs < lomax || kbs + 64 > himin) {
                const int clo0 = lo0 - kbs, chi0 = hi0 - kbs;
                const int clo1 = lo1 - kbs, chi1 = hi1 - kbs;
                #pragma unroll
                for (int j = 0; j < 8; j++) {
                    int cb = j * 8 + (lane & 3) * 2;
                    if (cb < clo0     || cb >= chi0)     s[j][0] = MASKV;
                    if (cb + 1 < clo0 || cb + 1 >= chi0) s[j][1] = MASKV;
                    if (cb < clo1     || cb >= chi1)     s[j][2] = MASKV;
                    if (cb + 1 < clo1 || cb + 1 >= chi1) s[j][3] = MASKV;
                }
            }

            // ---- fixed-max softmax: P = exp2(s); rowsum in f32 on FMA pipe ----
            float ps0 = 0.f, ps1 = 0.f;
            #pragma unroll
            for (int c = 0; c < 4; c++) {
                uint32_t vf[4][4];
                uint32_t vcbase = vbase + (uint32_t)(c * 2048);
                #pragma unroll
                for (int np = 0; np < 4; np++)
                    ldsm_x4t(vf[np][0], vf[np][1], vf[np][2], vf[np][3],
                             vcbase + (uint32_t)(((2 * np + vnsel) ^ swz) << 4));
                uint32_t pa[4];
                #pragma unroll
                for (int jj = 0; jj < 2; jj++) {
                    int j = 2 * c + jj;
                    float p0 = ex2(s[j][0]);
                    float p1 = ex2(s[j][1]);
                    float p2 = ex2(s[j][2]);
                    float p3 = ex2(s[j][3]);
                    ps0 += p0 + p1; ps1 += p2 + p3;
                    pa[2 * jj]     = packh2(p0, p1);
                    pa[2 * jj + 1] = packh2(p2, p3);
                }
                #pragma unroll
                for (int np = 0; np < 4; np++) {
                    mma_f16(o[2 * np],     pa, vf[np]);
                    mma_f16(o[2 * np + 1], pa, vf[np] + 2);
                }
            }
            l0r += ps0;
            l1r += ps1;
        }
    }

    // ---- epilogue: quad-reduce l (lanes share rows), normalize, store ----
    l0r += __shfl_xor_sync(0xffffffffu, l0r, 1);
    l0r += __shfl_xor_sync(0xffffffffu, l0r, 2);
    l1r += __shfl_xor_sync(0xffffffffu, l1r, 1);
    l1r += __shfl_xor_sync(0xffffffffu, l1r, 2);
    float inv0 = l0r > 0.f ? 1.f / l0r : 0.f;
    float inv1 = l1r > 0.f ? 1.f / l1r : 0.f;

    const int t0 = q0 + r0, t1 = t0 + 8;
    const int colb = (lane & 3) * 2;
    if (t0 < T) {
        float* op = out + (size_t)t0 * (HEADS * DIM) + h * DIM + colb;
        #pragma unroll
        for (int n = 0; n < 8; n++)
            *(float2*)(op + n * 8) = make_float2(o[n][0] * inv0, o[n][1] * inv0);
    }
    if (t1 < T) {
        float* op = out + (size_t)t1 * (HEADS * DIM) + h * DIM + colb;
        #pragma unroll
        for (int n = 0; n < 8; n++)
            *(float2*)(op + n * 8) = make_float2(o[n][2] * inv1, o[n][3] * inv1);
    }
}

// ---------------- launch ----------------
extern "C" void kernel_launch(void* const* d_in, const int* in_sizes, int n_in,
                              void* d_out, int out_size)
{
    const float* qkv = (const float*)d_in[0];
    const int*   cu  = (const int*)d_in[1];
    const int T    = in_sizes[0] / (3 * HEADS * DIM);
    const int nseg = in_sizes[1] - 1;

    static bool init = false;
    if (!init) {
        cudaFuncSetAttribute(attn_main, cudaFuncAttributeMaxDynamicSharedMemorySize, SMEM_BYTES);
        init = true;
    }

    prep<<<(T * HEADS * 16 + 255) / 256, 256>>>(qkv, T);
    attn_main<<<dim3((T + BM - 1) / BM, HEADS), NT, SMEM_BYTES>>>(cu, nseg, T, (float*)d_out);
}

// round 16
// speedup vs baseline: 1.6564x; 1.1395x over previous
#include <cuda_runtime.h>
#include <cuda_fp16.h>
#include <cstdint>

#define HEADS 8
#define DIM   64
#define TMAXP 4096
#define BM    128
#define BN    64
#define NT    128

// smem layout (bytes): swizzled 128B rows
#define S_QH 0
#define S_KV 16384            // + stage*KV_STAGE, 3 stages
#define KV_STAGE 16384
#define T_KH 0
#define T_VH 8192
#define S_RS 65536
#define S_RE 66048
#define SMEM_BYTES 66560

#define MASKV -3.0e38f

// ---------------- scratch (fp16) ----------------
__device__ __align__(16) __half g_Qh[(size_t)HEADS * TMAXP * DIM];
__device__ __align__(16) __half g_Kh[(size_t)HEADS * TMAXP * DIM];
__device__ __align__(16) __half g_Vh[(size_t)HEADS * TMAXP * DIM];

// ---------------- helpers ----------------
__device__ __forceinline__ float ex2(float x) {
    float r;
    asm("ex2.approx.ftz.f32 %0, %1;" : "=f"(r) : "f"(x));
    return r;
}
__device__ __forceinline__ uint32_t smem_u32(const void* p) {
    uint32_t a;
    asm("{ .reg .u64 t; cvta.to.shared.u64 t, %1; cvt.u32.u64 %0, t; }" : "=r"(a) : "l"(p));
    return a;
}
__device__ __forceinline__ void ldsm_x4(uint32_t& r0, uint32_t& r1, uint32_t& r2, uint32_t& r3, uint32_t a) {
    asm volatile("ldmatrix.sync.aligned.m8n8.x4.shared.b16 {%0,%1,%2,%3}, [%4];"
                 : "=r"(r0), "=r"(r1), "=r"(r2), "=r"(r3) : "r"(a));
}
__device__ __forceinline__ void ldsm_x4t(uint32_t& r0, uint32_t& r1, uint32_t& r2, uint32_t& r3, uint32_t a) {
    asm volatile("ldmatrix.sync.aligned.m8n8.x4.trans.shared.b16 {%0,%1,%2,%3}, [%4];"
                 : "=r"(r0), "=r"(r1), "=r"(r2), "=r"(r3) : "r"(a));
}
__device__ __forceinline__ void mma_f16(float* c, const uint32_t* a, const uint32_t* b) {
    asm volatile("mma.sync.aligned.m16n8k16.row.col.f32.f16.f16.f32 "
                 "{%0,%1,%2,%3}, {%4,%5,%6,%7}, {%8,%9}, {%0,%1,%2,%3};"
                 : "+f"(c[0]), "+f"(c[1]), "+f"(c[2]), "+f"(c[3])
                 : "r"(a[0]), "r"(a[1]), "r"(a[2]), "r"(a[3]), "r"(b[0]), "r"(b[1]));
}
// pack two floats to fp16x2 (lo = a, hi = b)
__device__ __forceinline__ uint32_t packh2(float a, float b) {
    uint32_t r;
    asm("cvt.rn.f16x2.f32 %0, %1, %2;" : "=r"(r) : "f"(b), "f"(a));
    return r;
}
#define CP_ASYNC(dst, src, sz) \
    asm volatile("cp.async.cg.shared.global [%0], [%1], 16, %2;" :: "r"(dst), "l"(src), "r"(sz))
#define CP_COMMIT() asm volatile("cp.async.commit_group;" ::: "memory")
#define CP_WAIT0()  asm volatile("cp.async.wait_group 0;" ::: "memory")
#define CP_WAIT1()  asm volatile("cp.async.wait_group 1;" ::: "memory")

// ---------------- prep: fp32 qkv -> fp16 (Q scaled, K, V) ----------------
__global__ void prep(const float* __restrict__ qkv, int T) {
    int idx = blockIdx.x * blockDim.x + threadIdx.x;
    if (idx >= T * HEADS * 16) return;
    int d4 = idx & 15;
    int h  = (idx >> 4) & (HEADS - 1);
    int t  = idx >> 7;
    const size_t gin = (size_t)t * 1536 + h * 64 + d4 * 4;
    const float4 q = *(const float4*)(qkv + gin);
    const float4 k = *(const float4*)(qkv + gin + 512);
    const float4 v = *(const float4*)(qkv + gin + 1024);
    size_t base = ((size_t)h * TMAXP + t) * DIM + d4 * 4;
    const float s = 0.125f * 1.4426950408889634f;  // 1/sqrt(64) * log2(e)
    *(uint2*)(g_Qh + base) = make_uint2(packh2(q.x * s, q.y * s), packh2(q.z * s, q.w * s));
    *(uint2*)(g_Kh + base) = make_uint2(packh2(k.x, k.y), packh2(k.z, k.w));
    *(uint2*)(g_Vh + base) = make_uint2(packh2(v.x, v.y), packh2(v.z, v.w));
}

// ---------------- main attention: 4 warps x 32 q-rows ----------------
__global__ __launch_bounds__(NT, 2)
void attn_main(const int* __restrict__ cu, int nseg, int T, float* __restrict__ out)
{
    extern __shared__ char smem[];
    const uint32_t sb = smem_u32(smem);
    const int tid = threadIdx.x, wid = tid >> 5, lane = tid & 31;
    const int q0 = blockIdx.x * BM;
    const int h  = blockIdx.y;
    int* rs_s = (int*)(smem + S_RS);
    int* re_s = (int*)(smem + S_RE);

    // warp owns m-tiles A (rows m0..m0+16) and B (rows m0+64..m0+80)
    const int m0 = wid * 16;

    // stage Q tile (128 rows x 8 chunks = 1024 uint4), swizzled
    {
        const uint4* qh = (const uint4*)(g_Qh + ((size_t)h * TMAXP + q0) * DIM);
        #pragma unroll
        for (int p = 0; p < 8; p++) {
            int i = tid + p * NT;
            int row = i >> 3, c = i & 7;
            uint32_t soff = (uint32_t)(row * 128 + ((c ^ (row & 7)) << 4));
            if (q0 + row < T) *(uint4*)(smem + S_QH + soff) = qh[i];
            else              *(uint4*)(smem + S_QH + soff) = make_uint4(0, 0, 0, 0);
        }
    }
    if (tid < BM) {
        int t = q0 + tid; if (t > T - 1) t = T - 1;
        int s = 0;
        for (int i = 0; i < nseg; i++) if (t >= cu[i]) s = i;
        rs_s[tid] = cu[s]; re_s[tid] = cu[s + 1];
    }
    __syncthreads();
    const int kvlo = rs_s[0];
    const int kvhi = re_s[BM - 1];

    const int r0 = m0 + (lane >> 2);
    const int lo0 = rs_s[r0],      hi0 = re_s[r0];
    const int lo1 = rs_s[r0 + 8],  hi1 = re_s[r0 + 8];
    const int lo2 = rs_s[r0 + 64], hi2 = re_s[r0 + 64];
    const int lo3 = rs_s[r0 + 72], hi3 = re_s[r0 + 72];
    int lomax = lo0 > lo1 ? lo0 : lo1;
    lomax = lomax > lo2 ? lomax : lo2;
    lomax = lomax > lo3 ? lomax : lo3;
    int himin = hi0 < hi1 ? hi0 : hi1;
    himin = himin < hi2 ? himin : hi2;
    himin = himin < hi3 ? himin : hi3;

    const __half* gKH = g_Kh + (size_t)h * TMAXP * DIM;
    const __half* gVH = g_Vh + (size_t)h * TMAXP * DIM;

    // cp.async staging geometry: 64 rows x 8 chunks per tensor, 128 threads
    // -> each thread: 4 rows per tensor (rows cprow + rr*16)
    const int cpc   = tid & 7;
    const int cprow = tid >> 3;           // 0..15
    const int cpg   = cprow * 64 + cpc * 8;

    // fragment address invariants
    const int swz = lane & 7;
    const uint32_t qrowA = (uint32_t)((m0 + (lane & 15)) * 128);
    const uint32_t qrowB = qrowA + 64 * 128;
    const int qcc = lane >> 4;
    const uint32_t krow4 = (uint32_t)((((lane >> 4) * 8) + (lane & 7)) * 128);
    const int khalf = (lane >> 3) & 1;
    const uint32_t vrow4 = (uint32_t)(((((lane >> 3) & 1) * 8) + (lane & 7)) * 128);
    const int vnsel = lane >> 4;

    // ---- hoist Q fragments for both m-tiles (loop-invariant) ----
    uint32_t qfA[4][4], qfB[4][4];
    #pragma unroll
    for (int c = 0; c < 4; c++) {
        uint32_t coff = (uint32_t)(((qcc + 2 * c) ^ swz) << 4);
        ldsm_x4(qfA[c][0], qfA[c][1], qfA[c][2], qfA[c][3], sb + S_QH + qrowA + coff);
        ldsm_x4(qfB[c][0], qfB[c][1], qfB[c][2], qfB[c][3], sb + S_QH + qrowB + coff);
    }

    float lA0 = 0.f, lA1 = 0.f, lB0 = 0.f, lB1 = 0.f;
    float oA[8][4], oB[8][4];
    #pragma unroll
    for (int n = 0; n < 8; n++)
        #pragma unroll
        for (int e = 0; e < 4; e++) { oA[n][e] = 0.f; oB[n][e] = 0.f; }

    const int nIter = (kvhi - kvlo + BN - 1) / BN;

    // prologue: stage tiles 0 and 1
    #pragma unroll
    for (int pre = 0; pre < 2; pre++) {
        if (pre < nIter) {
            const int kb = kvlo + pre * BN;
            uint32_t dbase = sb + S_KV + (uint32_t)(pre * KV_STAGE);
            #pragma unroll
            for (int rr = 0; rr < 4; rr++) {
                int row = cprow + rr * 16;
                uint32_t off = (uint32_t)(row * 128 + ((cpc ^ (row & 7)) << 4));
                int g = cpg + rr * 1024;
                int sz = (kb + row < kvhi) ? 16 : 0;
                CP_ASYNC(dbase + T_KH + off, gKH + (size_t)kb * DIM + g, sz);
                CP_ASYNC(dbase + T_VH + off, gVH + (size_t)kb * DIM + g, sz);
            }
        }
        CP_COMMIT();
    }

    for (int it = 0; it < nIter; it++) {
        const int kb = kvlo + it * BN;

        if (it + 1 < nIter) { CP_WAIT1(); } else { CP_WAIT0(); }
        __syncthreads();

        if (it + 2 < nIter) {
            const int kn = kb + 2 * BN;
            uint32_t dbase = sb + S_KV + (uint32_t)(((it + 2) % 3) * KV_STAGE);
            #pragma unroll
            for (int rr = 0; rr < 4; rr++) {
                int row = cprow + rr * 16;
                uint32_t off = (uint32_t)(row * 128 + ((cpc ^ (row & 7)) << 4));
                int g = cpg + rr * 1024;
                int sz = (kn + row < kvhi) ? 16 : 0;
                CP_ASYNC(dbase + T_KH + off, gKH + (size_t)kn * DIM + g, sz);
                CP_ASYNC(dbase + T_VH + off, gVH + (size_t)kn * DIM + g, sz);
            }
            CP_COMMIT();
        }

        const uint32_t kvb = sb + S_KV + (uint32_t)((it % 3) * KV_STAGE);
        const uint32_t kbase = kvb + T_KH + krow4;
        const uint32_t vbase = kvb + T_VH + vrow4;

        // ---- MMA1: S for both m-tiles; K fragments shared ----
        float sA[8][4], sB[8][4];
        #pragma unroll
        for (int n = 0; n < 8; n++)
            #pragma unroll
            for (int e = 0; e < 4; e++) { sA[n][e] = 0.f; sB[n][e] = 0.f; }

        #pragma unroll
        for (int c = 0; c < 4; c++) {
            const uint32_t kchunk = (uint32_t)(((khalf + 2 * c) ^ swz) << 4);
            uint32_t kf[4][4];
            #pragma unroll
            for (int jp = 0; jp < 4; jp++)
                ldsm_x4(kf[jp][0], kf[jp][1], kf[jp][2], kf[jp][3],
                        kbase + (uint32_t)(jp * 2048) + kchunk);
            #pragma unroll
            for (int jp = 0; jp < 4; jp++) {
                mma_f16(sA[2 * jp],     qfA[c], kf[jp]);
                mma_f16(sA[2 * jp + 1], qfA[c], kf[jp] + 2);
                mma_f16(sB[2 * jp],     qfB[c], kf[jp]);
                mma_f16(sB[2 * jp + 1], qfB[c], kf[jp] + 2);
            }
        }

        // ---- boundary tiles only: clamp invalid entries ----
        if (kb < lomax || kb + BN > himin) {
            const int clo0 = lo0 - kb, chi0 = hi0 - kb;
            const int clo1 = lo1 - kb, chi1 = hi1 - kb;
            const int clo2 = lo2 - kb, chi2 = hi2 - kb;
            const int clo3 = lo3 - kb, chi3 = hi3 - kb;
            #pragma unroll
            for (int j = 0; j < 8; j++) {
                int cb = j * 8 + (lane & 3) * 2;
                if (cb < clo0     || cb >= chi0)     sA[j][0] = MASKV;
                if (cb + 1 < clo0 || cb + 1 >= chi0) sA[j][1] = MASKV;
                if (cb < clo1     || cb >= chi1)     sA[j][2] = MASKV;
                if (cb + 1 < clo1 || cb + 1 >= chi1) sA[j][3] = MASKV;
                if (cb < clo2     || cb >= chi2)     sB[j][0] = MASKV;
                if (cb + 1 < clo2 || cb + 1 >= chi2) sB[j][1] = MASKV;
                if (cb < clo3     || cb >= chi3)     sB[j][2] = MASKV;
                if (cb + 1 < clo3 || cb + 1 >= chi3) sB[j][3] = MASKV;
            }
        }

        // ---- fixed-max softmax + MMA2; V fragments shared between tiles ----
        float psA0 = 0.f, psA1 = 0.f, psB0 = 0.f, psB1 = 0.f;
        #pragma unroll
        for (int c = 0; c < 4; c++) {
            uint32_t vf[4][4];
            uint32_t vcbase = vbase + (uint32_t)(c * 2048);
            #pragma unroll
            for (int np = 0; np < 4; np++)
                ldsm_x4t(vf[np][0], vf[np][1], vf[np][2], vf[np][3],
                         vcbase + (uint32_t)(((2 * np + vnsel) ^ swz) << 4));
            uint32_t paA[4], paB[4];
            #pragma unroll
            for (int jj = 0; jj < 2; jj++) {
                int j = 2 * c + jj;
                float a0 = ex2(sA[j][0]);
                float a1 = ex2(sA[j][1]);
                float a2 = ex2(sA[j][2]);
                float a3 = ex2(sA[j][3]);
                psA0 += a0 + a1; psA1 += a2 + a3;
                paA[2 * jj]     = packh2(a0, a1);
                paA[2 * jj + 1] = packh2(a2, a3);
                float b0 = ex2(sB[j][0]);
                float b1 = ex2(sB[j][1]);
                float b2 = ex2(sB[j][2]);
                float b3 = ex2(sB[j][3]);
                psB0 += b0 + b1; psB1 += b2 + b3;
                paB[2 * jj]     = packh2(b0, b1);
                paB[2 * jj + 1] = packh2(b2, b3);
            }
            #pragma unroll
            for (int np = 0; np < 4; np++) {
                mma_f16(oA[2 * np],     paA, vf[np]);
                mma_f16(oA[2 * np + 1], paA, vf[np] + 2);
                mma_f16(oB[2 * np],     paB, vf[np]);
                mma_f16(oB[2 * np + 1], paB, vf[np] + 2);
            }
        }
        lA0 += psA0; lA1 += psA1;
        lB0 += psB0; lB1 += psB1;
    }

    // ---- epilogue: quad-reduce l, normalize, store ----
    lA0 += __shfl_xor_sync(0xffffffffu, lA0, 1);
    lA0 += __shfl_xor_sync(0xffffffffu, lA0, 2);
    lA1 += __shfl_xor_sync(0xffffffffu, lA1, 1);
    lA1 += __shfl_xor_sync(0xffffffffu, lA1, 2);
    lB0 += __shfl_xor_sync(0xffffffffu, lB0, 1);
    lB0 += __shfl_xor_sync(0xffffffffu, lB0, 2);
    lB1 += __shfl_xor_sync(0xffffffffu, lB1, 1);
    lB1 += __shfl_xor_sync(0xffffffffu, lB1, 2);
    float invA0 = lA0 > 0.f ? 1.f / lA0 : 0.f;
    float invA1 = lA1 > 0.f ? 1.f / lA1 : 0.f;
    float invB0 = lB0 > 0.f ? 1.f / lB0 : 0.f;
    float invB1 = lB1 > 0.f ? 1.f / lB1 : 0.f;

    const int colb = (lane & 3) * 2;
    const int tA0 = q0 + r0, tA1 = tA0 + 8;
    const int tB0 = tA0 + 64, tB1 = tA0 + 72;
    if (tA0 < T) {
        float* op = out + (size_t)tA0 * (HEADS * DIM) + h * DIM + colb;
        #pragma unroll
        for (int n = 0; n < 8; n++)
            *(float2*)(op + n * 8) = make_float2(oA[n][0] * invA0, oA[n][1] * invA0);
    }
    if (tA1 < T) {
        float* op = out + (size_t)tA1 * (HEADS * DIM) + h * DIM + colb;
        #pragma unroll
        for (int n = 0; n < 8; n++)
            *(float2*)(op + n * 8) = make_float2(oA[n][2] * invA1, oA[n][3] * invA1);
    }
    if (tB0 < T) {
        float* op = out + (size_t)tB0 * (HEADS * DIM) + h * DIM + colb;
        #pragma unroll
        for (int n = 0; n < 8; n++)
            *(float2*)(op + n * 8) = make_float2(oB[n][0] * invB0, oB[n][1] * invB0);
    }
    if (tB1 < T) {
        float* op = out + (size_t)tB1 * (HEADS * DIM) + h * DIM + colb;
        #pragma unroll
        for (int n = 0; n < 8; n++)
            *(float2*)(op + n * 8) = make_float2(oB[n][2] * invB1, oB[n][3] * invB1);
    }
}

// ---------------- launch ----------------
extern "C" void kernel_launch(void* const* d_in, const int* in_sizes, int n_in,
                              void* d_out, int out_size)
{
    const float* qkv = (const float*)d_in[0];
    const int*   cu  = (const int*)d_in[1];
    const int T    = in_sizes[0] / (3 * HEADS * DIM);
    const int nseg = in_sizes[1] - 1;

    static bool init = false;
    if (!init) {
        cudaFuncSetAttribute(attn_main, cudaFuncAttributeMaxDynamicSharedMemorySize, SMEM_BYTES);
        init = true;
    }

    prep<<<(T * HEADS * 16 + 255) / 256, 256>>>(qkv, T);
    attn_main<<<dim3((T + BM - 1) / BM, HEADS), NT, SMEM_BYTES>>>(cu, nseg, T, (float*)d_out);
}